// round 1
// baseline (speedup 1.0000x reference)
#include <cuda_runtime.h>
#include <cuda_bf16.h>

// Problem constants
#define NV_TOT 20000
#define IN_DIM 150
#define H_DIM  64
#define P_DIM  5
#define T_DIM  16
#define K_DIM  3
#define O_DIM  128
#define PT_DIM 80      // P*T
#define CONN_STRIDE 240 // P*T*K

// Scratch (device globals; no allocation allowed)
__device__ float g_h[NV_TOT * H_DIM];           // 5.12 MB hidden activations
__device__ float g_wgt[PT_DIM * H_DIM * O_DIM]; // 2.62 MB transposed Wg: [pt][h][o]

// ---------------------------------------------------------------------------
// packed f32x2 helpers (Blackwell FFMA2 — 2 FMAs per instruction)
// ---------------------------------------------------------------------------
__device__ __forceinline__ unsigned long long pack2(float a, float b) {
    unsigned long long r;
    asm("mov.b64 %0, {%1, %2};" : "=l"(r) : "f"(a), "f"(b));
    return r;
}
__device__ __forceinline__ void ffma2(unsigned long long& d,
                                      unsigned long long a,
                                      unsigned long long b) {
    asm("fma.rn.f32x2 %0, %1, %2, %0;" : "+l"(d) : "l"(a), "l"(b));
}
__device__ __forceinline__ float2 unpack2(unsigned long long v) {
    float2 r;
    asm("mov.b64 {%0, %1}, %2;" : "=f"(r.x), "=f"(r.y) : "l"(v));
    return r;
}

// ---------------------------------------------------------------------------
// Kernel 0: transpose Wg[o][h][p][t] -> g_wgt[pt][h][o]
// grid: PT_DIM*H_DIM = 5120 blocks, 128 threads (o)
// ---------------------------------------------------------------------------
__global__ void __launch_bounds__(128) k_transpose(const float* __restrict__ Wg) {
    int o = threadIdx.x;
    int b = blockIdx.x;          // b = c*64 + h
    int c = b >> 6;
    int h = b & 63;
    g_wgt[b * O_DIM + o] = Wg[(o * H_DIM + h) * PT_DIM + c];
}

// ---------------------------------------------------------------------------
// Kernel 1: h = relu(x @ W1^T)  -> g_h[v][h]
// grid: 625 blocks x 256 threads; 32 vertices per block
// ---------------------------------------------------------------------------
__global__ void __launch_bounds__(256) k_hidden(const float* __restrict__ x,
                                                const float* __restrict__ W1) {
    __shared__ float W1t[IN_DIM * H_DIM];  // [i][h], 38.4 KB
    int t = threadIdx.x;
    for (int idx = t; idx < IN_DIM * H_DIM; idx += 256) {
        int i = idx >> 6;
        int h = idx & 63;
        W1t[idx] = W1[h * IN_DIM + i];
    }
    __syncthreads();

    int vbase = blockIdx.x * 32;
    int h  = t & 63;
    int vg = t >> 6;  // 0..3, covers vertices vg*8 .. vg*8+7
    const float* xrow = x + (long)(vbase + vg * 8) * IN_DIM;

    float acc[8];
#pragma unroll
    for (int j = 0; j < 8; j++) acc[j] = 0.0f;

    for (int i = 0; i < IN_DIM; i += 2) {
        float w0 = W1t[i * H_DIM + h];
        float w1 = W1t[(i + 1) * H_DIM + h];
#pragma unroll
        for (int j = 0; j < 8; j++) {
            float2 xv = *(const float2*)(xrow + j * IN_DIM + i);
            acc[j] = fmaf(xv.x, w0, acc[j]);
            acc[j] = fmaf(xv.y, w1, acc[j]);
        }
    }
#pragma unroll
    for (int j = 0; j < 8; j++) {
        g_h[(long)(vbase + vg * 8 + j) * H_DIM + h] = fmaxf(acc[j], 0.0f);
    }
}

// ---------------------------------------------------------------------------
// Kernel 2: main fused gather + GEMM + bias + L2-normalize
// grid: 313 blocks x 256 threads; 64 vertices per block
// Shared: patch[64v][64h] (16KB) + Bs[64h][128o] (32KB) + conn staging (1.5KB)
// Thread micro-tile: 8 vertices x 4 outputs, accumulated as f32x2 pairs.
// ---------------------------------------------------------------------------
#define SMEM_MAIN_BYTES ((64 * 64 + 64 * 128) * 4 + 64 * 3 * 4 * 2)

__global__ void __launch_bounds__(256) k_main(const int*   __restrict__ conn_idx,
                                              const float* __restrict__ conn_w,
                                              const float* __restrict__ bg,
                                              float*       __restrict__ out) {
    extern __shared__ float smem[];
    float* patch = smem;                 // [v][h] : 64*64
    float* Bs    = smem + 64 * 64;       // [h][o] : 64*128
    int*   sidx  = (int*)(smem + 64 * 64 + 64 * 128);  // [v][k] : 64*3
    float* sw    = (float*)(sidx + 64 * 3);            // [v][k] : 64*3

    int t = threadIdx.x;
    int vbase = blockIdx.x * 64;
    int nv = NV_TOT - vbase;
    if (nv > 64) nv = 64;

    int ob = t & 31;   // output block: o = ob*4 .. ob*4+3
    int vb = t >> 5;   // warp id = vertex block: v = vb*8 .. vb*8+7

    unsigned long long acc[8][2];
#pragma unroll
    for (int j = 0; j < 8; j++) { acc[j][0] = 0ULL; acc[j][1] = 0ULL; }

    for (int c = 0; c < PT_DIM; c++) {
        __syncthreads();  // previous chunk fully consumed

        // stage connectivity for this chunk: 64 vertices x 3 neighbors
        if (t < 192) {
            int v = t / 3;
            int k = t - v * 3;
            if (v < nv) {
                long off = (long)(vbase + v) * CONN_STRIDE + c * 3 + k;
                sidx[t] = conn_idx[off];
                sw[t]   = conn_w[off];
            } else {
                sidx[t] = 0;
                sw[t]   = 0.0f;
            }
        }
        // stage Wg chunk: 64h x 128o = 8192 floats, coalesced float4
        {
            const float4* src = (const float4*)(g_wgt + (long)c * (H_DIM * O_DIM));
            float4* dst = (float4*)Bs;
#pragma unroll
            for (int i = 0; i < 8; i++) dst[t + i * 256] = __ldg(&src[t + i * 256]);
        }
        __syncthreads();  // sidx/sw ready

        // build patch tile: patch[v][h] = sum_k w * g_h[idx][h]
#pragma unroll
        for (int i = 0; i < 16; i++) {
            int e = t + i * 256;
            int v = e >> 6;
            int h = e & 63;
            int i0 = sidx[v * 3 + 0];
            int i1 = sidx[v * 3 + 1];
            int i2 = sidx[v * 3 + 2];
            float s = sw[v * 3 + 0] * __ldg(&g_h[(long)i0 * H_DIM + h])
                    + sw[v * 3 + 1] * __ldg(&g_h[(long)i1 * H_DIM + h])
                    + sw[v * 3 + 2] * __ldg(&g_h[(long)i2 * H_DIM + h]);
            patch[v * 64 + h] = s;
        }
        __syncthreads();  // patch + Bs ready

        // GEMM: acc[8v][4o] += patch[64v x 64h] * Bs[64h x 128o]
#pragma unroll 4
        for (int h = 0; h < 64; h++) {
            float4 b = *(const float4*)&Bs[h * O_DIM + ob * 4];
            unsigned long long b01 = pack2(b.x, b.y);
            unsigned long long b23 = pack2(b.z, b.w);
            const float* prow = &patch[vb * 8 * 64 + h];
#pragma unroll
            for (int j = 0; j < 8; j++) {
                float av = prow[j * 64];           // warp-uniform broadcast
                unsigned long long aa = pack2(av, av);
                ffma2(acc[j][0], aa, b01);
                ffma2(acc[j][1], aa, b23);
            }
        }
    }

    // Epilogue: bias, per-vertex L2 norm (warp holds one 8-vertex group), store
    float4 bgv = *(const float4*)&bg[ob * 4];
#pragma unroll
    for (int j = 0; j < 8; j++) {
        float2 p0 = unpack2(acc[j][0]);
        float2 p1 = unpack2(acc[j][1]);
        float v0 = p0.x + bgv.x;
        float v1 = p0.y + bgv.y;
        float v2 = p1.x + bgv.z;
        float v3 = p1.y + bgv.w;
        float part = v0 * v0 + v1 * v1 + v2 * v2 + v3 * v3;
#pragma unroll
        for (int off = 16; off > 0; off >>= 1)
            part += __shfl_xor_sync(0xffffffffu, part, off);
        float inv = rsqrtf(part);
        int v = vbase + vb * 8 + j;
        if (v < NV_TOT) {
            float4 o4;
            o4.x = v0 * inv; o4.y = v1 * inv; o4.z = v2 * inv; o4.w = v3 * inv;
            *(float4*)&out[(long)v * O_DIM + ob * 4] = o4;
        }
    }
}

// ---------------------------------------------------------------------------
extern "C" void kernel_launch(void* const* d_in, const int* in_sizes, int n_in,
                              void* d_out, int out_size) {
    const float* x    = (const float*)d_in[0];
    const int*   cidx = (const int*)d_in[1];
    const float* cw   = (const float*)d_in[2];
    const float* W1   = (const float*)d_in[3];
    const float* Wg   = (const float*)d_in[4];
    const float* bg   = (const float*)d_in[5];
    float* out = (float*)d_out;

    cudaFuncSetAttribute(k_main, cudaFuncAttributeMaxDynamicSharedMemorySize,
                         SMEM_MAIN_BYTES);

    k_transpose<<<PT_DIM * H_DIM, 128>>>(Wg);
    k_hidden<<<NV_TOT / 32, 256>>>(x, W1);
    k_main<<<(NV_TOT + 63) / 64, 256, SMEM_MAIN_BYTES>>>(cidx, cw, bg, out);
}

// round 2
// speedup vs baseline: 1.4337x; 1.4337x over previous
#include <cuda_runtime.h>
#include <cuda_bf16.h>

// Problem constants
#define NV_TOT 20000
#define IN_DIM 150
#define H_DIM  64
#define P_DIM  5
#define T_DIM  16
#define K_DIM  3
#define O_DIM  128
#define PT_DIM 80       // P*T
#define CONN_STRIDE 240 // P*T*K

#define VT 32           // vertices per block in k_main
#define PROW 68         // padded patch row (floats): distinct banks for vg broadcasts

// Scratch (device globals; no allocation allowed)
__device__ float g_h[NV_TOT * H_DIM];           // 5.12 MB hidden activations
__device__ float g_wgt[PT_DIM * H_DIM * O_DIM]; // 2.62 MB transposed Wg: [pt][h][o]

// ---------------------------------------------------------------------------
// packed f32x2 helpers (Blackwell FFMA2 — 2 FMAs per instruction)
// ---------------------------------------------------------------------------
__device__ __forceinline__ unsigned long long pack2(float a, float b) {
    unsigned long long r;
    asm("mov.b64 %0, {%1, %2};" : "=l"(r) : "f"(a), "f"(b));
    return r;
}
__device__ __forceinline__ void ffma2(unsigned long long& d,
                                      unsigned long long a,
                                      unsigned long long b) {
    asm("fma.rn.f32x2 %0, %1, %2, %0;" : "+l"(d) : "l"(a), "l"(b));
}
__device__ __forceinline__ float2 unpack2(unsigned long long v) {
    float2 r;
    asm("mov.b64 {%0, %1}, %2;" : "=f"(r.x), "=f"(r.y) : "l"(v));
    return r;
}

// ---------------------------------------------------------------------------
// Kernel 0: transpose Wg[o][h][p][t] -> g_wgt[pt][h][o]
// ---------------------------------------------------------------------------
__global__ void __launch_bounds__(128) k_transpose(const float* __restrict__ Wg) {
    int o = threadIdx.x;
    int b = blockIdx.x;          // b = c*64 + h
    int c = b >> 6;
    int h = b & 63;
    g_wgt[b * O_DIM + o] = Wg[(o * H_DIM + h) * PT_DIM + c];
}

// ---------------------------------------------------------------------------
// Kernel 1: h = relu(x @ W1^T)  -> g_h[v][h]
// ---------------------------------------------------------------------------
__global__ void __launch_bounds__(256) k_hidden(const float* __restrict__ x,
                                                const float* __restrict__ W1) {
    __shared__ float W1t[IN_DIM * H_DIM];  // [i][h]
    int t = threadIdx.x;
    for (int idx = t; idx < IN_DIM * H_DIM; idx += 256) {
        int i = idx >> 6;
        int h = idx & 63;
        W1t[idx] = W1[h * IN_DIM + i];
    }
    __syncthreads();

    int vbase = blockIdx.x * 32;
    int h  = t & 63;
    int vg = t >> 6;  // 0..3
    const float* xrow = x + (long)(vbase + vg * 8) * IN_DIM;

    float acc[8];
#pragma unroll
    for (int j = 0; j < 8; j++) acc[j] = 0.0f;

    for (int i = 0; i < IN_DIM; i += 2) {
        float w0 = W1t[i * H_DIM + h];
        float w1 = W1t[(i + 1) * H_DIM + h];
#pragma unroll
        for (int j = 0; j < 8; j++) {
            float2 xv = *(const float2*)(xrow + j * IN_DIM + i);
            acc[j] = fmaf(xv.x, w0, acc[j]);
            acc[j] = fmaf(xv.y, w1, acc[j]);
        }
    }
#pragma unroll
    for (int j = 0; j < 8; j++) {
        g_h[(long)(vbase + vg * 8 + j) * H_DIM + h] = fmaxf(acc[j], 0.0f);
    }
}

// ---------------------------------------------------------------------------
// Kernel 2: fused gather + GEMM + bias + L2-normalize
// 128 threads, block tile 32v x 128o, micro-tile 4v x 8o.
// Thread map: og = t&15 (o = og*4 in [0,64) and 64+og*4), vg = t>>4 (v = vg*4).
// Per 2h: B = 4x LDS.128 (16 lanes contiguous 256B -> 2 wavefronts each),
//         A = 4x LDS.64 broadcast (padded rows -> distinct banks, 1 wf each)
//         => 12 smem wavefronts per 2048 warp-FMAs -> FMA-bound.
// ---------------------------------------------------------------------------
#define SMEM_MAIN_BYTES ((VT * PROW + 64 * 128) * 4 + VT * 3 * 4 * 2)

__global__ void __launch_bounds__(128, 5) k_main(const int*   __restrict__ conn_idx,
                                                 const float* __restrict__ conn_w,
                                                 const float* __restrict__ bg,
                                                 float*       __restrict__ out) {
    extern __shared__ float smem[];
    float* patch = smem;                     // [VT][PROW]
    float* Bs    = smem + VT * PROW;         // [64][128]
    int*   sidx  = (int*)(Bs + 64 * 128);    // [VT][3]
    float* sw    = (float*)(sidx + VT * 3);  // [VT][3]

    int t = threadIdx.x;
    int vbase = blockIdx.x * VT;

    int og = t & 15;   // o-group: o = og*4 (+{0..3}) and 64+og*4 (+{0..3})
    int vg = t >> 4;   // 0..7 -> v = vg*4 .. vg*4+3
    int v0 = vg * 4;

    unsigned long long acc[4][4];
#pragma unroll
    for (int j = 0; j < 4; j++)
#pragma unroll
        for (int p = 0; p < 4; p++) acc[j][p] = 0ULL;

    for (int c = 0; c < PT_DIM; c++) {
        __syncthreads();  // previous chunk fully consumed

        // stage connectivity: VT vertices x 3 neighbors
        if (t < VT * 3) {
            int v = t / 3;
            int k = t - v * 3;
            long off = (long)(vbase + v) * CONN_STRIDE + c * 3 + k;
            sidx[t] = conn_idx[off];
            sw[t]   = conn_w[off];
        }
        // stage Wg chunk: 64h x 128o = 2048 float4
        {
            const float4* src = (const float4*)(g_wgt + (long)c * (H_DIM * O_DIM));
            float4* dst = (float4*)Bs;
#pragma unroll
            for (int i = 0; i < 16; i++) dst[t + i * 128] = src[t + i * 128];
        }
        __syncthreads();  // sidx/sw ready

        // build patch tile: patch[v][h] = sum_k w * g_h[idx][h]
#pragma unroll
        for (int i = 0; i < 16; i++) {
            int e = t + i * 128;
            int v = e >> 6;
            int h = e & 63;
            int i0 = sidx[v * 3 + 0];
            int i1 = sidx[v * 3 + 1];
            int i2 = sidx[v * 3 + 2];
            float s = sw[v * 3 + 0] * g_h[(long)i0 * H_DIM + h]
                    + sw[v * 3 + 1] * g_h[(long)i1 * H_DIM + h]
                    + sw[v * 3 + 2] * g_h[(long)i2 * H_DIM + h];
            patch[v * PROW + h] = s;
        }
        __syncthreads();  // patch + Bs ready

        // GEMM: acc[4v][8o] += patch[32v x 64h] * Bs[64h x 128o]
#pragma unroll 4
        for (int h2 = 0; h2 < 64; h2 += 2) {
            ulonglong2 bA0 = *(const ulonglong2*)&Bs[h2 * O_DIM + og * 4];
            ulonglong2 bB0 = *(const ulonglong2*)&Bs[h2 * O_DIM + 64 + og * 4];
            ulonglong2 bA1 = *(const ulonglong2*)&Bs[(h2 + 1) * O_DIM + og * 4];
            ulonglong2 bB1 = *(const ulonglong2*)&Bs[(h2 + 1) * O_DIM + 64 + og * 4];
#pragma unroll
            for (int j = 0; j < 4; j++) {
                float2 a = *(const float2*)&patch[(v0 + j) * PROW + h2];
                unsigned long long a0 = pack2(a.x, a.x);
                unsigned long long a1 = pack2(a.y, a.y);
                ffma2(acc[j][0], a0, bA0.x);
                ffma2(acc[j][1], a0, bA0.y);
                ffma2(acc[j][2], a0, bB0.x);
                ffma2(acc[j][3], a0, bB0.y);
                ffma2(acc[j][0], a1, bA1.x);
                ffma2(acc[j][1], a1, bA1.y);
                ffma2(acc[j][2], a1, bB1.x);
                ffma2(acc[j][3], a1, bB1.y);
            }
        }
    }

    // Epilogue: bias, per-vertex L2 norm (reduce across 16 og lanes), store
    float4 bg0 = *(const float4*)&bg[og * 4];
    float4 bg1 = *(const float4*)&bg[64 + og * 4];
#pragma unroll
    for (int j = 0; j < 4; j++) {
        float2 p0 = unpack2(acc[j][0]);
        float2 p1 = unpack2(acc[j][1]);
        float2 p2 = unpack2(acc[j][2]);
        float2 p3 = unpack2(acc[j][3]);
        float v0a = p0.x + bg0.x, v1a = p0.y + bg0.y;
        float v2a = p1.x + bg0.z, v3a = p1.y + bg0.w;
        float v0b = p2.x + bg1.x, v1b = p2.y + bg1.y;
        float v2b = p3.x + bg1.z, v3b = p3.y + bg1.w;
        float part = v0a * v0a + v1a * v1a + v2a * v2a + v3a * v3a
                   + v0b * v0b + v1b * v1b + v2b * v2b + v3b * v3b;
        // reduce across the 16 og lanes (stays inside each 16-lane half)
#pragma unroll
        for (int off = 8; off > 0; off >>= 1)
            part += __shfl_xor_sync(0xffffffffu, part, off);
        float inv = rsqrtf(part);
        int v = vbase + v0 + j;
        float4 oA, oB;
        oA.x = v0a * inv; oA.y = v1a * inv; oA.z = v2a * inv; oA.w = v3a * inv;
        oB.x = v0b * inv; oB.y = v1b * inv; oB.z = v2b * inv; oB.w = v3b * inv;
        *(float4*)&out[(long)v * O_DIM + og * 4]      = oA;
        *(float4*)&out[(long)v * O_DIM + 64 + og * 4] = oB;
    }
}

// ---------------------------------------------------------------------------
extern "C" void kernel_launch(void* const* d_in, const int* in_sizes, int n_in,
                              void* d_out, int out_size) {
    const float* x    = (const float*)d_in[0];
    const int*   cidx = (const int*)d_in[1];
    const float* cw   = (const float*)d_in[2];
    const float* W1   = (const float*)d_in[3];
    const float* Wg   = (const float*)d_in[4];
    const float* bg   = (const float*)d_in[5];
    float* out = (float*)d_out;

    cudaFuncSetAttribute(k_main, cudaFuncAttributeMaxDynamicSharedMemorySize,
                         SMEM_MAIN_BYTES);

    k_transpose<<<PT_DIM * H_DIM, 128>>>(Wg);
    k_hidden<<<NV_TOT / 32, 256>>>(x, W1);
    k_main<<<NV_TOT / VT, 128, SMEM_MAIN_BYTES>>>(cidx, cw, bg, out);
}

// round 7
// speedup vs baseline: 2.6012x; 1.8143x over previous
#include <cuda_runtime.h>
#include <cuda_bf16.h>
#include <cstdint>

// Problem constants
#define NV_TOT 20000
#define IN_DIM 150
#define H_DIM  64
#define O_DIM  128
#define PT_DIM 80
#define CONN_STRIDE 240   // PT_DIM * 3

#define MTILE 64
#define NBLK  ((NV_TOT + MTILE - 1) / MTILE)   // 313

// Tile pitch: 36 words (144B) per row -> conflict-free frag reads & stores
#define PITCH_W 36

// SMEM layout (bytes from dynamic base)
#define OFF_BG      0                     // 128 floats
#define OFF_ROWSUM  512                   // 64 floats
#define A_HI        1024                  // 64 rows * 144B = 9216
#define A_LO        (A_HI + 64 * 144)     // 10240
#define B_HI        (A_LO + 64 * 144)     // 19456: 128 rows * 144B = 18432
#define B_LO        (B_HI + 128 * 144)    // 37888
#define SMEM_TOTAL  (B_LO + 128 * 144)    // 56320

// Scratch (16B-aligned: g_h is read with 64-bit vector loads)
__device__ __align__(16) float    g_h[NV_TOT * H_DIM];      // fp32 hidden
__device__ __align__(16) uint32_t g_bh[PT_DIM * 4096];      // bf16x2 B hi, [pt][o][kpair]
__device__ __align__(16) uint32_t g_bl[PT_DIM * 4096];      // bf16x2 B lo

// ---------------------------------------------------------------------------
__device__ __forceinline__ void mma16816(float* d, const uint32_t* a, const uint32_t* b) {
    asm volatile("mma.sync.aligned.m16n8k16.row.col.f32.bf16.bf16.f32 "
                 "{%0,%1,%2,%3}, {%4,%5,%6,%7}, {%8,%9}, {%0,%1,%2,%3};"
                 : "+f"(d[0]), "+f"(d[1]), "+f"(d[2]), "+f"(d[3])
                 : "r"(a[0]), "r"(a[1]), "r"(a[2]), "r"(a[3]),
                   "r"(b[0]), "r"(b[1]));
}

// ---------------------------------------------------------------------------
// prep B: split Wg[o][h][pt] -> bf16 hi/lo, row-major [pt][o][kpair(=h/2)]
// ---------------------------------------------------------------------------
__global__ void __launch_bounds__(256) k_prepB(const float* __restrict__ Wg) {
    int pt = blockIdx.x;
    int t = threadIdx.x;
#pragma unroll
    for (int i = 0; i < 16; i++) {
        int item = t + i * 256;           // item = o*32 + hp
        int o = item >> 5, hp = item & 31;
        float w0 = Wg[(o * H_DIM + 2 * hp) * PT_DIM + pt];
        float w1 = Wg[(o * H_DIM + 2 * hp + 1) * PT_DIM + pt];
        __nv_bfloat16 h0 = __float2bfloat16(w0);
        __nv_bfloat16 h1 = __float2bfloat16(w1);
        __nv_bfloat16 l0 = __float2bfloat16(w0 - __bfloat162float(h0));
        __nv_bfloat16 l1 = __float2bfloat16(w1 - __bfloat162float(h1));
        __nv_bfloat162 hh; hh.x = h0; hh.y = h1;
        __nv_bfloat162 ll; ll.x = l0; ll.y = l1;
        g_bh[pt * 4096 + item] = *(uint32_t*)&hh;
        g_bl[pt * 4096 + item] = *(uint32_t*)&ll;
    }
}

// ---------------------------------------------------------------------------
// h = relu(x @ W1^T) -> g_h (fp32)
// ---------------------------------------------------------------------------
__global__ void __launch_bounds__(256) k_hidden(const float* __restrict__ x,
                                                const float* __restrict__ W1) {
    __shared__ float W1t[IN_DIM * H_DIM];
    int t = threadIdx.x;
    for (int idx = t; idx < IN_DIM * H_DIM; idx += 256) {
        int i = idx >> 6, h = idx & 63;
        W1t[idx] = W1[h * IN_DIM + i];
    }
    __syncthreads();

    int vbase = blockIdx.x * 32;
    int h = t & 63;
    int vg = t >> 6;
    const float* xrow = x + (long)(vbase + vg * 8) * IN_DIM;
    float acc[8];
#pragma unroll
    for (int j = 0; j < 8; j++) acc[j] = 0.0f;
    for (int i = 0; i < IN_DIM; i += 2) {
        float w0 = W1t[i * H_DIM + h];
        float w1 = W1t[(i + 1) * H_DIM + h];
#pragma unroll
        for (int j = 0; j < 8; j++) {
            float2 xv = *(const float2*)(xrow + j * IN_DIM + i);
            acc[j] = fmaf(xv.x, w0, acc[j]);
            acc[j] = fmaf(xv.y, w1, acc[j]);
        }
    }
#pragma unroll
    for (int j = 0; j < 8; j++)
        g_h[(long)(vbase + vg * 8 + j) * H_DIM + h] = fmaxf(acc[j], 0.0f);
}

// ---------------------------------------------------------------------------
// Main: 64v M-tile, 256 threads (8 warps, each 32v x 32o).
// 80 K-chunks of 64; 3-term bf16-split mma.sync; single-buffer smem with
// register-pipelined B prefetch; manual fragment LDS (no ldmatrix/cp.async).
// ---------------------------------------------------------------------------
__global__ void __launch_bounds__(256, 2) k_main(const int*   __restrict__ conn_idx,
                                                 const float* __restrict__ conn_w,
                                                 const float* __restrict__ bg,
                                                 float*       __restrict__ out) {
    extern __shared__ char smem_c[];
    float* s_bg = (float*)(smem_c + OFF_BG);
    float* s_rs = (float*)(smem_c + OFF_ROWSUM);

    int t = threadIdx.x;
    int wid = t >> 5, l = t & 31;
    int vbase = blockIdx.x * MTILE;

    if (t < 128) s_bg[t] = bg[t];
    if (t < MTILE) s_rs[t] = 0.0f;

    int m0 = (wid & 1) * 32;
    int n0 = (wid >> 1) * 32;
    int gr = l >> 2, q = l & 3;

    float acc[2][4][4];
#pragma unroll
    for (int a1 = 0; a1 < 2; a1++)
#pragma unroll
        for (int a2 = 0; a2 < 4; a2++)
#pragma unroll
            for (int a3 = 0; a3 < 4; a3++) acc[a1][a2][a3] = 0.0f;

    float4 pb[8];   // B prefetch regs: 4 hi + 4 lo

    auto ldgB = [&](int c) {
        const float4* sh = (const float4*)(g_bh + c * 4096);
        const float4* sl = (const float4*)(g_bl + c * 4096);
#pragma unroll
        for (int j = 0; j < 4; j++) {
            pb[j]     = sh[t + j * 256];
            pb[4 + j] = sl[t + j * 256];
        }
    };
    auto stsB = [&]() {
#pragma unroll
        for (int j = 0; j < 4; j++) {
            int e = t + j * 256;
            int row = e >> 3, wo = (e & 7) * 4;
            *(float4*)(smem_c + B_HI + (row * PITCH_W + wo) * 4) = pb[j];
            *(float4*)(smem_c + B_LO + (row * PITCH_W + wo) * 4) = pb[4 + j];
        }
    };
    auto gatherA = [&](int c) {
#pragma unroll 4
        for (int i = 0; i < 8; i++) {
            int vv = wid + 8 * i;          // 0..63, lane-uniform conn
            int gv = vbase + vv;
            int i0 = 0, i1 = 0, i2 = 0;
            float w0 = 0.f, w1 = 0.f, w2 = 0.f;
            if (gv < NV_TOT) {
                long cb = (long)gv * CONN_STRIDE + c * 3;
                i0 = conn_idx[cb]; i1 = conn_idx[cb + 1]; i2 = conn_idx[cb + 2];
                w0 = conn_w[cb];   w1 = conn_w[cb + 1];   w2 = conn_w[cb + 2];
            }
            float2 h0 = *((const float2*)(g_h + (long)i0 * H_DIM) + l);
            float2 h1 = *((const float2*)(g_h + (long)i1 * H_DIM) + l);
            float2 h2 = *((const float2*)(g_h + (long)i2 * H_DIM) + l);
            float ax = fmaf(w2, h2.x, fmaf(w1, h1.x, w0 * h0.x));
            float ay = fmaf(w2, h2.y, fmaf(w1, h1.y, w0 * h0.y));
            __nv_bfloat16 hx = __float2bfloat16(ax);
            __nv_bfloat16 hy = __float2bfloat16(ay);
            __nv_bfloat16 lx = __float2bfloat16(ax - __bfloat162float(hx));
            __nv_bfloat16 ly = __float2bfloat16(ay - __bfloat162float(hy));
            __nv_bfloat162 hh; hh.x = hx; hh.y = hy;
            __nv_bfloat162 ll; ll.x = lx; ll.y = ly;
            *(uint32_t*)(smem_c + A_HI + (vv * PITCH_W + l) * 4) = *(uint32_t*)&hh;
            *(uint32_t*)(smem_c + A_LO + (vv * PITCH_W + l) * 4) = *(uint32_t*)&ll;
        }
    };
    auto mma_chunk = [&]() {
        const uint32_t* ah_s = (const uint32_t*)(smem_c + A_HI);
        const uint32_t* al_s = (const uint32_t*)(smem_c + A_LO);
        const uint32_t* bh_s = (const uint32_t*)(smem_c + B_HI);
        const uint32_t* bl_s = (const uint32_t*)(smem_c + B_LO);
#pragma unroll
        for (int ks = 0; ks < 4; ks++) {
            int kc = ks * 8 + q;
            uint32_t aH[2][4], aL[2][4], bH[4][2], bL[4][2];
#pragma unroll
            for (int mt = 0; mt < 2; mt++) {
                int ar = (m0 + mt * 16 + gr) * PITCH_W;
                aH[mt][0] = ah_s[ar + kc];
                aH[mt][1] = ah_s[ar + 8 * PITCH_W + kc];
                aH[mt][2] = ah_s[ar + kc + 4];
                aH[mt][3] = ah_s[ar + 8 * PITCH_W + kc + 4];
                aL[mt][0] = al_s[ar + kc];
                aL[mt][1] = al_s[ar + 8 * PITCH_W + kc];
                aL[mt][2] = al_s[ar + kc + 4];
                aL[mt][3] = al_s[ar + 8 * PITCH_W + kc + 4];
            }
#pragma unroll
            for (int nt = 0; nt < 4; nt++) {
                int br = (n0 + nt * 8 + gr) * PITCH_W;
                bH[nt][0] = bh_s[br + kc];
                bH[nt][1] = bh_s[br + kc + 4];
                bL[nt][0] = bl_s[br + kc];
                bL[nt][1] = bl_s[br + kc + 4];
            }
#pragma unroll
            for (int mt = 0; mt < 2; mt++)
#pragma unroll
                for (int nt = 0; nt < 4; nt++) {
                    mma16816(acc[mt][nt], aH[mt], bH[nt]);   // hi*hi
                    mma16816(acc[mt][nt], aH[mt], bL[nt]);   // hi*lo
                    mma16816(acc[mt][nt], aL[mt], bH[nt]);   // lo*hi
                }
        }
    };

    // pipeline: LDG(c+1) in flight while MMA(c) runs
    ldgB(0);
    for (int c = 0; c < PT_DIM; c++) {
        stsB();
        gatherA(c);
        __syncthreads();
        if (c + 1 < PT_DIM) ldgB(c + 1);
        mma_chunk();
        __syncthreads();
    }

    // epilogue: bias, rowsums, L2-normalize, store
#pragma unroll
    for (int mt = 0; mt < 2; mt++)
#pragma unroll
        for (int nt = 0; nt < 4; nt++)
#pragma unroll
            for (int p = 0; p < 4; p++)
                acc[mt][nt][p] += s_bg[n0 + nt * 8 + q * 2 + (p & 1)];

#pragma unroll
    for (int mt = 0; mt < 2; mt++)
#pragma unroll
        for (int qh = 0; qh < 2; qh++) {
            float part = 0.f;
#pragma unroll
            for (int nt = 0; nt < 4; nt++) {
                float v0 = acc[mt][nt][qh * 2 + 0];
                float v1 = acc[mt][nt][qh * 2 + 1];
                part = fmaf(v0, v0, part);
                part = fmaf(v1, v1, part);
            }
            part += __shfl_xor_sync(0xffffffffu, part, 1);
            part += __shfl_xor_sync(0xffffffffu, part, 2);
            if (q == 0) {
                int row = m0 + mt * 16 + gr + qh * 8;
                atomicAdd(&s_rs[row], part);
            }
        }
    __syncthreads();

#pragma unroll
    for (int mt = 0; mt < 2; mt++)
#pragma unroll
        for (int qh = 0; qh < 2; qh++) {
            int row = m0 + mt * 16 + gr + qh * 8;
            int row_g = vbase + row;
            if (row_g < NV_TOT) {
                float inv = rsqrtf(s_rs[row]);
#pragma unroll
                for (int nt = 0; nt < 4; nt++) {
                    float2 o2;
                    o2.x = acc[mt][nt][qh * 2 + 0] * inv;
                    o2.y = acc[mt][nt][qh * 2 + 1] * inv;
                    *(float2*)&out[(long)row_g * O_DIM + n0 + nt * 8 + q * 2] = o2;
                }
            }
        }
}

// ---------------------------------------------------------------------------
extern "C" void kernel_launch(void* const* d_in, const int* in_sizes, int n_in,
                              void* d_out, int out_size) {
    const float* x    = (const float*)d_in[0];
    const int*   cidx = (const int*)d_in[1];
    const float* cw   = (const float*)d_in[2];
    const float* W1   = (const float*)d_in[3];
    const float* Wg   = (const float*)d_in[4];
    const float* bg   = (const float*)d_in[5];
    float* out = (float*)d_out;

    cudaFuncSetAttribute(k_main, cudaFuncAttributeMaxDynamicSharedMemorySize,
                         SMEM_TOTAL);

    k_prepB<<<PT_DIM, 256>>>(Wg);
    k_hidden<<<NV_TOT / 32, 256>>>(x, W1);
    k_main<<<NBLK, 256, SMEM_TOTAL>>>(cidx, cw, bg, out);
}

// round 8
// speedup vs baseline: 2.7784x; 1.0681x over previous
#include <cuda_runtime.h>
#include <cuda_bf16.h>
#include <cstdint>

// Problem constants
#define NV_TOT 20000
#define IN_DIM 150
#define H_DIM  64
#define O_DIM  128
#define PT_DIM 80
#define CONN_STRIDE 240   // PT_DIM * 3

#define MTILE 32
#define NBLK  (NV_TOT / MTILE)   // 625, exact

// SMEM layout (bytes from dynamic base)
#define OFF_BG  0                 // 128 floats
#define OFF_RS  512               // 32 floats
#define A_HI    1024              // 2 mtiles * 4 ks * 32 slots * 16B = 4096
#define A_LO    5120
#define B_HI    9216              // 16 ntiles * 4 ks * 32 lanes * 8B = 16384
#define B_LO    25600
#define SMEM_TOTAL 41984

// Scratch (16B-aligned: g_h read with 64-bit vector loads)
__device__ __align__(16) float    g_h[NV_TOT * H_DIM];   // fp32 hidden
__device__ __align__(16) uint32_t g_bh[PT_DIM * 4096];   // B hi, fragment layout
__device__ __align__(16) uint32_t g_bl[PT_DIM * 4096];   // B lo, fragment layout

// ---------------------------------------------------------------------------
__device__ __forceinline__ void mma16816(float* d, const uint32_t* a, const uint32_t* b) {
    asm volatile("mma.sync.aligned.m16n8k16.row.col.f32.bf16.bf16.f32 "
                 "{%0,%1,%2,%3}, {%4,%5,%6,%7}, {%8,%9}, {%0,%1,%2,%3};"
                 : "+f"(d[0]), "+f"(d[1]), "+f"(d[2]), "+f"(d[3])
                 : "r"(a[0]), "r"(a[1]), "r"(a[2]), "r"(a[3]),
                   "r"(b[0]), "r"(b[1]));
}

// ---------------------------------------------------------------------------
// prep B: split Wg[o][h][pt] -> bf16 hi/lo directly in MMA *fragment* layout:
// word = ((ntile*4 + ks)*32 + gro*4 + q)*2 + r4
// where o = ntile*8+gro, kpair hp = ks*8 + r4*4 + q.
// grid 320 = 80 pt * 4 parts.
// ---------------------------------------------------------------------------
__global__ void __launch_bounds__(256) k_prepB(const float* __restrict__ Wg) {
    int b = blockIdx.x;
    int pt = b >> 2;
    int base = (b & 3) * 1024 + threadIdx.x;
#pragma unroll
    for (int i = 0; i < 4; i++) {
        int item = base + i * 256;            // item = o*32 + hp
        int o = item >> 5, hp = item & 31;
        float w0 = Wg[(o * H_DIM + 2 * hp) * PT_DIM + pt];
        float w1 = Wg[(o * H_DIM + 2 * hp + 1) * PT_DIM + pt];
        __nv_bfloat16 h0 = __float2bfloat16(w0);
        __nv_bfloat16 h1 = __float2bfloat16(w1);
        __nv_bfloat16 l0 = __float2bfloat16(w0 - __bfloat162float(h0));
        __nv_bfloat16 l1 = __float2bfloat16(w1 - __bfloat162float(h1));
        __nv_bfloat162 hh; hh.x = h0; hh.y = h1;
        __nv_bfloat162 ll; ll.x = l0; ll.y = l1;
        int ntile = o >> 3, gro = o & 7;
        int ks = hp >> 3, r4 = (hp >> 2) & 1, q = hp & 3;
        int word = ((ntile * 4 + ks) * 32 + gro * 4 + q) * 2 + r4;
        g_bh[pt * 4096 + word] = *(uint32_t*)&hh;
        g_bl[pt * 4096 + word] = *(uint32_t*)&ll;
    }
}

// ---------------------------------------------------------------------------
// h = relu(x @ W1^T) -> g_h (fp32)
// ---------------------------------------------------------------------------
__global__ void __launch_bounds__(256) k_hidden(const float* __restrict__ x,
                                                const float* __restrict__ W1) {
    __shared__ float W1t[IN_DIM * H_DIM];
    int t = threadIdx.x;
    for (int idx = t; idx < IN_DIM * H_DIM; idx += 256) {
        int i = idx >> 6, h = idx & 63;
        W1t[idx] = W1[h * IN_DIM + i];
    }
    __syncthreads();

    int vbase = blockIdx.x * 32;
    int h = t & 63;
    int vg = t >> 6;
    const float* xrow = x + (long)(vbase + vg * 8) * IN_DIM;
    float acc[8];
#pragma unroll
    for (int j = 0; j < 8; j++) acc[j] = 0.0f;
    for (int i = 0; i < IN_DIM; i += 2) {
        float w0 = W1t[i * H_DIM + h];
        float w1 = W1t[(i + 1) * H_DIM + h];
#pragma unroll
        for (int j = 0; j < 8; j++) {
            float2 xv = *(const float2*)(xrow + j * IN_DIM + i);
            acc[j] = fmaf(xv.x, w0, acc[j]);
            acc[j] = fmaf(xv.y, w1, acc[j]);
        }
    }
#pragma unroll
    for (int j = 0; j < 8; j++)
        g_h[(long)(vbase + vg * 8 + j) * H_DIM + h] = fmaxf(acc[j], 0.0f);
}

// ---------------------------------------------------------------------------
// Main: 32v M-tile per block (exact 625 blocks), 256 threads, occupancy 4.
// 8 warps, warp tile 16v x 32o. Fragment-layout smem:
//   A: lane l's 4 regs contiguous -> one LDS.128 (slot XOR ks*5 swizzle)
//   B: lane l's 2 regs contiguous -> one LDS.64 (verbatim copy from g_bh/g_bl)
// 3-term bf16-split mma.sync.
// ---------------------------------------------------------------------------
__global__ void __launch_bounds__(256, 4) k_main(const int*   __restrict__ conn_idx,
                                                 const float* __restrict__ conn_w,
                                                 const float* __restrict__ bg,
                                                 float*       __restrict__ out) {
    extern __shared__ char smem_c[];
    float* s_bg = (float*)(smem_c + OFF_BG);
    float* s_rs = (float*)(smem_c + OFF_RS);

    int t = threadIdx.x;
    int wid = t >> 5, l = t & 31;
    int vbase = blockIdx.x * MTILE;

    if (t < 128) s_bg[t] = bg[t];
    if (t < MTILE) s_rs[t] = 0.0f;

    int mtile = wid & 1;       // m0 = mtile*16
    int nq = wid >> 1;         // n0 = nq*32, ntiles nq*4 .. nq*4+3
    int gr = l >> 2, q = l & 3;

    float acc[4][4];
#pragma unroll
    for (int a2 = 0; a2 < 4; a2++)
#pragma unroll
        for (int a3 = 0; a3 < 4; a3++) acc[a2][a3] = 0.0f;

    for (int c = 0; c < PT_DIM; c++) {
        // stage B (both planes): verbatim coalesced copy, already fragment layout
        {
            const float4* sh = (const float4*)(g_bh + c * 4096);
            const float4* sl = (const float4*)(g_bl + c * 4096);
            float4* dh = (float4*)(smem_c + B_HI);
            float4* dl = (float4*)(smem_c + B_LO);
#pragma unroll
            for (int j = 0; j < 4; j++) {
                dh[t + j * 256] = sh[t + j * 256];
                dl[t + j * 256] = sl[t + j * 256];
            }
        }
        // gather A rows, split to bf16 hi/lo, store in fragment layout
#pragma unroll
        for (int i = 0; i < 4; i++) {
            int vv = wid + 8 * i;          // 0..31, lane-uniform conn
            long cb = (long)(vbase + vv) * CONN_STRIDE + c * 3;
            int i0 = conn_idx[cb], i1 = conn_idx[cb + 1], i2 = conn_idx[cb + 2];
            float w0 = conn_w[cb], w1 = conn_w[cb + 1], w2 = conn_w[cb + 2];
            float2 h0 = *((const float2*)(g_h + (long)i0 * H_DIM) + l);
            float2 h1 = *((const float2*)(g_h + (long)i1 * H_DIM) + l);
            float2 h2 = *((const float2*)(g_h + (long)i2 * H_DIM) + l);
            float ax = fmaf(w2, h2.x, fmaf(w1, h1.x, w0 * h0.x));
            float ay = fmaf(w2, h2.y, fmaf(w1, h1.y, w0 * h0.y));
            __nv_bfloat16 hx = __float2bfloat16(ax);
            __nv_bfloat16 hy = __float2bfloat16(ay);
            __nv_bfloat16 lx = __float2bfloat16(ax - __bfloat162float(hx));
            __nv_bfloat16 ly = __float2bfloat16(ay - __bfloat162float(hy));
            __nv_bfloat162 hh; hh.x = hx; hh.y = hy;
            __nv_bfloat162 ll; ll.x = lx; ll.y = ly;
            // fragment coords for element (row vv, kpair l)
            int mt2 = vv >> 4, r = vv & 15, grv = r & 7, half = r >> 3;
            int ks = l >> 3, r4 = (l >> 2) & 1, qq = l & 3;
            int slot = (grv * 4 + qq) ^ ((ks * 5) & 31);
            int word = ((mt2 * 4 + ks) * 32 + slot) * 4 + r4 * 2 + half;
            ((uint32_t*)(smem_c + A_HI))[word] = *(uint32_t*)&hh;
            ((uint32_t*)(smem_c + A_LO))[word] = *(uint32_t*)&ll;
        }
        __syncthreads();

        // MMA: acc += A[16x64] * B[32x64]^T, 3 split terms
#pragma unroll
        for (int ks = 0; ks < 4; ks++) {
            int aslot = l ^ ((ks * 5) & 31);
            uint4 aH = ((const uint4*)(smem_c + A_HI))[(mtile * 4 + ks) * 32 + aslot];
            uint4 aL = ((const uint4*)(smem_c + A_LO))[(mtile * 4 + ks) * 32 + aslot];
            uint2 bH[4], bL[4];
#pragma unroll
            for (int nt = 0; nt < 4; nt++) {
                int nti = nq * 4 + nt;
                bH[nt] = ((const uint2*)(smem_c + B_HI))[(nti * 4 + ks) * 32 + l];
                bL[nt] = ((const uint2*)(smem_c + B_LO))[(nti * 4 + ks) * 32 + l];
            }
#pragma unroll
            for (int nt = 0; nt < 4; nt++) {
                mma16816(acc[nt], (const uint32_t*)&aH, (const uint32_t*)&bH[nt]); // hi*hi
                mma16816(acc[nt], (const uint32_t*)&aH, (const uint32_t*)&bL[nt]); // hi*lo
                mma16816(acc[nt], (const uint32_t*)&aL, (const uint32_t*)&bH[nt]); // lo*hi
            }
        }
        __syncthreads();
    }

    // epilogue: bias, rowsums, L2-normalize, store
#pragma unroll
    for (int nt = 0; nt < 4; nt++)
#pragma unroll
        for (int p = 0; p < 4; p++)
            acc[nt][p] += s_bg[nq * 32 + nt * 8 + q * 2 + (p & 1)];

#pragma unroll
    for (int qh = 0; qh < 2; qh++) {
        float part = 0.f;
#pragma unroll
        for (int nt = 0; nt < 4; nt++) {
            float v0 = acc[nt][qh * 2 + 0];
            float v1 = acc[nt][qh * 2 + 1];
            part = fmaf(v0, v0, part);
            part = fmaf(v1, v1, part);
        }
        part += __shfl_xor_sync(0xffffffffu, part, 1);
        part += __shfl_xor_sync(0xffffffffu, part, 2);
        if (q == 0) atomicAdd(&s_rs[mtile * 16 + gr + qh * 8], part);
    }
    __syncthreads();

#pragma unroll
    for (int qh = 0; qh < 2; qh++) {
        int row = mtile * 16 + gr + qh * 8;
        float inv = rsqrtf(s_rs[row]);
#pragma unroll
        for (int nt = 0; nt < 4; nt++) {
            float2 o2;
            o2.x = acc[nt][qh * 2 + 0] * inv;
            o2.y = acc[nt][qh * 2 + 1] * inv;
            *(float2*)&out[(long)(vbase + row) * O_DIM + nq * 32 + nt * 8 + q * 2] = o2;
        }
    }
}

// ---------------------------------------------------------------------------
extern "C" void kernel_launch(void* const* d_in, const int* in_sizes, int n_in,
                              void* d_out, int out_size) {
    const float* x    = (const float*)d_in[0];
    const int*   cidx = (const int*)d_in[1];
    const float* cw   = (const float*)d_in[2];
    const float* W1   = (const float*)d_in[3];
    const float* Wg   = (const float*)d_in[4];
    const float* bg   = (const float*)d_in[5];
    float* out = (float*)d_out;

    cudaFuncSetAttribute(k_main, cudaFuncAttributeMaxDynamicSharedMemorySize,
                         SMEM_TOTAL);

    k_prepB<<<PT_DIM * 4, 256>>>(Wg);
    k_hidden<<<NV_TOT / 32, 256>>>(x, W1);
    k_main<<<NBLK, 256, SMEM_TOTAL>>>(cidx, cw, bg, out);
}

// round 9
// speedup vs baseline: 3.6176x; 1.3020x over previous
#include <cuda_runtime.h>
#include <cuda_fp16.h>
#include <cstdint>

// Problem constants
#define NV_TOT 20000
#define IN_DIM 150
#define H_DIM  64
#define O_DIM  128
#define PT_DIM 80
#define CONN_STRIDE 240   // PT_DIM * 3

#define MTILE 32
#define NBLK  (NV_TOT / MTILE)   // 625, exact

// SMEM layout (bytes from dynamic base)
#define OFF_BG  0                 // 128 floats
#define OFF_RS  512               // 32 floats
#define OFF_BUF 1024
// per buffer: A_HI(4K) A_LO(4K) B(16K) = 24K
#define A_HI_O  0
#define A_LO_O  4096
#define B_O     8192
#define BUF_STRIDE 24576
#define SMEM_TOTAL (1024 + 2 * BUF_STRIDE)   // 50176 -> occ 4 (200.7K/SM)

// Scratch (16B-aligned: g_h read with 64-bit vector loads)
__device__ __align__(16) float    g_h[NV_TOT * H_DIM];   // fp32 hidden
__device__ __align__(16) uint32_t g_bf[PT_DIM * 4096];   // B fp16, fragment layout

// ---------------------------------------------------------------------------
__device__ __forceinline__ void mma16816(float* d, const uint32_t* a, const uint32_t* b) {
    asm volatile("mma.sync.aligned.m16n8k16.row.col.f32.f16.f16.f32 "
                 "{%0,%1,%2,%3}, {%4,%5,%6,%7}, {%8,%9}, {%0,%1,%2,%3};"
                 : "+f"(d[0]), "+f"(d[1]), "+f"(d[2]), "+f"(d[3])
                 : "r"(a[0]), "r"(a[1]), "r"(a[2]), "r"(a[3]),
                   "r"(b[0]), "r"(b[1]));
}

// ---------------------------------------------------------------------------
// prep B: Wg[o][h][pt] -> fp16, MMA fragment layout:
// word = ((ntile*4 + ks)*32 + gro*4 + q)*2 + r4
// where o = ntile*8+gro, kpair hp = ks*8 + r4*4 + q.
// ---------------------------------------------------------------------------
__global__ void __launch_bounds__(256) k_prepB(const float* __restrict__ Wg) {
    int b = blockIdx.x;
    int pt = b >> 2;
    int base = (b & 3) * 1024 + threadIdx.x;
#pragma unroll
    for (int i = 0; i < 4; i++) {
        int item = base + i * 256;            // item = o*32 + hp
        int o = item >> 5, hp = item & 31;
        float w0 = Wg[(o * H_DIM + 2 * hp) * PT_DIM + pt];
        float w1 = Wg[(o * H_DIM + 2 * hp + 1) * PT_DIM + pt];
        __half2 hh = __floats2half2_rn(w0, w1);
        int ntile = o >> 3, gro = o & 7;
        int ks = hp >> 3, r4 = (hp >> 2) & 1, q = hp & 3;
        int word = ((ntile * 4 + ks) * 32 + gro * 4 + q) * 2 + r4;
        g_bf[pt * 4096 + word] = *(uint32_t*)&hh;
    }
}

// ---------------------------------------------------------------------------
// h = relu(x @ W1^T) -> g_h (fp32)
// ---------------------------------------------------------------------------
__global__ void __launch_bounds__(256) k_hidden(const float* __restrict__ x,
                                                const float* __restrict__ W1) {
    __shared__ float W1t[IN_DIM * H_DIM];
    int t = threadIdx.x;
    for (int idx = t; idx < IN_DIM * H_DIM; idx += 256) {
        int i = idx >> 6, h = idx & 63;
        W1t[idx] = W1[h * IN_DIM + i];
    }
    __syncthreads();

    int vbase = blockIdx.x * 32;
    int h = t & 63;
    int vg = t >> 6;
    const float* xrow = x + (long)(vbase + vg * 8) * IN_DIM;
    float acc[8];
#pragma unroll
    for (int j = 0; j < 8; j++) acc[j] = 0.0f;
    for (int i = 0; i < IN_DIM; i += 2) {
        float w0 = W1t[i * H_DIM + h];
        float w1 = W1t[(i + 1) * H_DIM + h];
#pragma unroll
        for (int j = 0; j < 8; j++) {
            float2 xv = *(const float2*)(xrow + j * IN_DIM + i);
            acc[j] = fmaf(xv.x, w0, acc[j]);
            acc[j] = fmaf(xv.y, w1, acc[j]);
        }
    }
#pragma unroll
    for (int j = 0; j < 8; j++)
        g_h[(long)(vbase + vg * 8 + j) * H_DIM + h] = fmaxf(acc[j], 0.0f);
}

// ---------------------------------------------------------------------------
// Main: 32v M-tile (625 exact blocks), 256 threads, occ 4, double-buffered.
// fp16 2-term split: A = Ah + Al (both fp16), B single fp16.
// D = Ah*B + Al*B  -> 2 MMAs per (ks, ntile), 32 HMMA/warp/chunk.
// ---------------------------------------------------------------------------
__global__ void __launch_bounds__(256, 4) k_main(const int*   __restrict__ conn_idx,
                                                 const float* __restrict__ conn_w,
                                                 const float* __restrict__ bg,
                                                 float*       __restrict__ out) {
    extern __shared__ char smem_c[];
    float* s_bg = (float*)(smem_c + OFF_BG);
    float* s_rs = (float*)(smem_c + OFF_RS);

    int t = threadIdx.x;
    int wid = t >> 5, l = t & 31;
    int vbase = blockIdx.x * MTILE;

    if (t < 128) s_bg[t] = bg[t];
    if (t < MTILE) s_rs[t] = 0.0f;

    int mtile = wid & 1;       // m0 = mtile*16
    int nq = wid >> 1;         // n0 = nq*32
    int gr = l >> 2, q = l & 3;

    float acc[4][4];
#pragma unroll
    for (int a2 = 0; a2 < 4; a2++)
#pragma unroll
        for (int a3 = 0; a3 < 4; a3++) acc[a2][a3] = 0.0f;

    // stage chunk c into buffer bsel
    auto stage = [&](int c, int bsel) {
        char* buf = smem_c + OFF_BUF + bsel * BUF_STRIDE;
        // B: verbatim coalesced copy (fragment layout), 16KB
        {
            const float4* src = (const float4*)(g_bf + c * 4096);
            float4* dst = (float4*)(buf + B_O);
#pragma unroll
            for (int j = 0; j < 4; j++) dst[t + j * 256] = src[t + j * 256];
        }
        // A gather + fp16 hi/lo split, fragment layout
#pragma unroll
        for (int i = 0; i < 4; i++) {
            int vv = wid + 8 * i;          // 0..31, lane-uniform conn
            long cb = (long)(vbase + vv) * CONN_STRIDE + c * 3;
            int i0 = conn_idx[cb], i1 = conn_idx[cb + 1], i2 = conn_idx[cb + 2];
            float w0 = conn_w[cb], w1 = conn_w[cb + 1], w2 = conn_w[cb + 2];
            float2 h0 = *((const float2*)(g_h + (long)i0 * H_DIM) + l);
            float2 h1 = *((const float2*)(g_h + (long)i1 * H_DIM) + l);
            float2 h2 = *((const float2*)(g_h + (long)i2 * H_DIM) + l);
            float ax = fmaf(w2, h2.x, fmaf(w1, h1.x, w0 * h0.x));
            float ay = fmaf(w2, h2.y, fmaf(w1, h1.y, w0 * h0.y));
            __half hx = __float2half_rn(ax);
            __half hy = __float2half_rn(ay);
            __half lx = __float2half_rn(ax - __half2float(hx));
            __half ly = __float2half_rn(ay - __half2float(hy));
            __half2 hh; hh.x = hx; hh.y = hy;
            __half2 ll; ll.x = lx; ll.y = ly;
            // fragment coords for element (row vv, kpair l)
            int mt2 = vv >> 4, r = vv & 15, grv = r & 7, half = r >> 3;
            int ks = l >> 3, r4 = (l >> 2) & 1, qq = l & 3;
            int slot = (grv * 4 + qq) ^ ((ks * 5) & 31);
            int word = ((mt2 * 4 + ks) * 32 + slot) * 4 + r4 * 2 + half;
            ((uint32_t*)(buf + A_HI_O))[word] = *(uint32_t*)&hh;
            ((uint32_t*)(buf + A_LO_O))[word] = *(uint32_t*)&ll;
        }
    };

    auto mma_chunk = [&](int bsel) {
        const char* buf = smem_c + OFF_BUF + bsel * BUF_STRIDE;
#pragma unroll
        for (int ks = 0; ks < 4; ks++) {
            int aslot = l ^ ((ks * 5) & 31);
            uint4 aH = ((const uint4*)(buf + A_HI_O))[(mtile * 4 + ks) * 32 + aslot];
            uint4 aL = ((const uint4*)(buf + A_LO_O))[(mtile * 4 + ks) * 32 + aslot];
            uint2 bF[4];
#pragma unroll
            for (int nt = 0; nt < 4; nt++)
                bF[nt] = ((const uint2*)(buf + B_O))[((nq * 4 + nt) * 4 + ks) * 32 + l];
#pragma unroll
            for (int nt = 0; nt < 4; nt++) {
                mma16816(acc[nt], (const uint32_t*)&aH, (const uint32_t*)&bF[nt]);
                mma16816(acc[nt], (const uint32_t*)&aL, (const uint32_t*)&bF[nt]);
            }
        }
    };

    // pipeline: one sync per chunk; stage(c+1) overwrites the buffer whose
    // MMA finished before the previous sync.
    stage(0, 0);
    __syncthreads();
    for (int c = 0; c < PT_DIM; c++) {
        int bsel = c & 1;
        if (c + 1 < PT_DIM) stage(c + 1, bsel ^ 1);
        mma_chunk(bsel);
        __syncthreads();
    }

    // epilogue: bias, rowsums, L2-normalize, store
#pragma unroll
    for (int nt = 0; nt < 4; nt++)
#pragma unroll
        for (int p = 0; p < 4; p++)
            acc[nt][p] += s_bg[nq * 32 + nt * 8 + q * 2 + (p & 1)];

#pragma unroll
    for (int qh = 0; qh < 2; qh++) {
        float part = 0.f;
#pragma unroll
        for (int nt = 0; nt < 4; nt++) {
            float v0 = acc[nt][qh * 2 + 0];
            float v1 = acc[nt][qh * 2 + 1];
            part = fmaf(v0, v0, part);
            part = fmaf(v1, v1, part);
        }
        part += __shfl_xor_sync(0xffffffffu, part, 1);
        part += __shfl_xor_sync(0xffffffffu, part, 2);
        if (q == 0) atomicAdd(&s_rs[mtile * 16 + gr + qh * 8], part);
    }
    __syncthreads();

#pragma unroll
    for (int qh = 0; qh < 2; qh++) {
        int row = mtile * 16 + gr + qh * 8;
        float inv = rsqrtf(s_rs[row]);
#pragma unroll
        for (int nt = 0; nt < 4; nt++) {
            float2 o2;
            o2.x = acc[nt][qh * 2 + 0] * inv;
            o2.y = acc[nt][qh * 2 + 1] * inv;
            *(float2*)&out[(long)(vbase + row) * O_DIM + nq * 32 + nt * 8 + q * 2] = o2;
        }
    }
}

// ---------------------------------------------------------------------------
extern "C" void kernel_launch(void* const* d_in, const int* in_sizes, int n_in,
                              void* d_out, int out_size) {
    const float* x    = (const float*)d_in[0];
    const int*   cidx = (const int*)d_in[1];
    const float* cw   = (const float*)d_in[2];
    const float* W1   = (const float*)d_in[3];
    const float* Wg   = (const float*)d_in[4];
    const float* bg   = (const float*)d_in[5];
    float* out = (float*)d_out;

    cudaFuncSetAttribute(k_main, cudaFuncAttributeMaxDynamicSharedMemorySize,
                         SMEM_TOTAL);

    k_prepB<<<PT_DIM * 4, 256>>>(Wg);
    k_hidden<<<NV_TOT / 32, 256>>>(x, W1);
    k_main<<<NBLK, 256, SMEM_TOTAL>>>(cidx, cw, bg, out);
}